// round 14
// baseline (speedup 1.0000x reference)
#include <cuda_runtime.h>
#include <cuda_fp16.h>

// ---------------------------------------------------------------------------
// CustomGraphConv on GB300 — R14: R10 baseline + f32x2 packed-FMA precompute.
//
//   msg[e,o]  = sum_{a,i} edge_attr[e,a] * W[a,o,i] * x[src_e, i]
//   aggr[n,o] = segment_sum over dst ; out = relu(aggr + bias)
//
// R11/R13 lesson: precompute is at its FFMA instruction-issue floor (~15us
// of pure FMA issue). fma.rn.f32x2 (Blackwell packed fp32, PTX-only) halves
// the FFMA stream; packing along i means W/x LDG.128 already deliver f32x2
// operands with zero extra pack instructions.
// Edge kernel frozen from R10 (48.5us, ~4 wavefronts/edge ≈ floor).
// ---------------------------------------------------------------------------

#define MAX_NODES 100000

// layout: [n][c=16][a=8] fp16, chunk c holds o = (c<8) ? 2c : 2(c-8)+1
__device__ __half g_yh[MAX_NODES * 128];   // 25.6 MB (L2-resident)

__device__ __forceinline__ unsigned long long ffma2(unsigned long long a,
                                                    unsigned long long b,
                                                    unsigned long long c) {
    unsigned long long d;
    asm("fma.rn.f32x2 %0, %1, %2, %3;" : "=l"(d) : "l"(a), "l"(b), "l"(c));
    return d;
}

// ---------------------------------------------------------------------------
// init halves of out with bias (harness poisons d_out with 0xAA). Split so
// the edge kernel stays launch #4 (the ncu capture slot).
// ---------------------------------------------------------------------------
__global__ void init_out_kernel(float4* __restrict__ out,
                                const float* __restrict__ bias,
                                int base, int n4) {
    int i = base + blockIdx.x * blockDim.x + threadIdx.x;
    if (i < n4) out[i] = ((const float4*)bias)[i & 3];
}

// ---------------------------------------------------------------------------
// P1: y[n][c(o)][a] = dot(W[a][o][:], x[n][:]). 4 nodes per thread
// (lane-strided), W row loads warp-uniform (broadcast, L1-resident).
// Dot products computed as f32x2 lanes over the i-dimension:
//   acc2 += w[2i,2i+1] * x[2i,2i+1]   (8 FFMA2 per (o,a,node))
// then one unpack + FADD folds the two halves.
// ---------------------------------------------------------------------------
__global__ void __launch_bounds__(128)
precompute_y_kernel(const float* __restrict__ x,
                    const float* __restrict__ W,
                    int N) {
    int lane = threadIdx.x & 31;
    int warp = (blockIdx.x * blockDim.x + threadIdx.x) >> 5;
    int n0 = warp * 128 + lane;

    // x rows as 8 f32x2 values per node
    unsigned long long xv[4][8];
    int nidx[4];
#pragma unroll
    for (int nn = 0; nn < 4; ++nn) {
        int n = n0 + 32 * nn;
        if (n >= N) n = N - 1;       // duplicate writes of same data: benign
        nidx[nn] = n;
        const ulonglong2* xp = (const ulonglong2*)x + (long long)n * 4;
#pragma unroll
        for (int q = 0; q < 4; ++q) {
            ulonglong2 v = xp[q];
            xv[nn][2 * q]     = v.x;
            xv[nn][2 * q + 1] = v.y;
        }
    }

    const ulonglong2* W2 = (const ulonglong2*)W;  // row (a,o): 4 ulonglong2

#pragma unroll 2
    for (int o = 0; o < 16; ++o) {
        float acc[4][8];
#pragma unroll
        for (int a = 0; a < 8; ++a) {
            int row = a * 16 + o;
            unsigned long long w[8];
#pragma unroll
            for (int q = 0; q < 4; ++q) {
                ulonglong2 v = W2[row * 4 + q];   // warp-uniform LDG.128
                w[2 * q]     = v.x;
                w[2 * q + 1] = v.y;
            }
#pragma unroll
            for (int nn = 0; nn < 4; ++nn) {
                unsigned long long acc2 = 0ULL;   // (0.0f, 0.0f)
#pragma unroll
                for (int q = 0; q < 8; ++q)
                    acc2 = ffma2(w[q], xv[nn][q], acc2);
                float lo, hi;
                asm("mov.b64 {%0, %1}, %2;" : "=f"(lo), "=f"(hi) : "l"(acc2));
                acc[nn][a] = lo + hi;
            }
        }
        // parity-permuted chunk: even o -> chunks 0..7, odd o -> chunks 8..15
        int c = (o & 1) * 8 + (o >> 1);
#pragma unroll
        for (int nn = 0; nn < 4; ++nn) {
            __half2 h0 = __floats2half2_rn(acc[nn][0], acc[nn][1]);
            __half2 h1 = __floats2half2_rn(acc[nn][2], acc[nn][3]);
            __half2 h2 = __floats2half2_rn(acc[nn][4], acc[nn][5]);
            __half2 h3 = __floats2half2_rn(acc[nn][6], acc[nn][7]);
            uint4 u;
            u.x = *(unsigned*)&h0;
            u.y = *(unsigned*)&h1;
            u.z = *(unsigned*)&h2;
            u.w = *(unsigned*)&h3;
            ((uint4*)g_yh)[(long long)nidx[nn] * 16 + c] = u;
        }
    }
}

// ---------------------------------------------------------------------------
// P2 (frozen from R10): 8 lanes/edge, 8 edges/warp.
// Lane s loads chunks {s, s+8}: one 128B line each (2 wavefronts/edge).
// Chunk s = o=2s (all 8 a-values); chunk s+8 = o=2s+1. Register dot with
// ea[e][0..8]. ZERO shfl. ONE red.global.add.v2.f32 per lane at out[dst][2s]
// (the 8 lanes' reds form one contiguous 64B burst).
// ---------------------------------------------------------------------------
__global__ void edge_scatter_kernel(const int* __restrict__ ei,
                                    const float* __restrict__ eattr,
                                    float* __restrict__ out,
                                    int E) {
    int lane = threadIdx.x & 31;
    int warp = (blockIdx.x * blockDim.x + threadIdx.x) >> 5;
    int g = lane >> 3;   // edge slot within warp (0..3)
    int s = lane & 7;    // sublane within edge

#pragma unroll
    for (int t = 0; t < 2; ++t) {
        int e = warp * 8 + t * 4 + g;
        if (e >= E) break;  // uniform across the 8-lane group

        int src = ei[e];
        const uint4* yv = (const uint4*)g_yh + (long long)src * 16;
        const float4* ea4 = (const float4*)(eattr + (long long)e * 8);
        float4 ea0 = ea4[0];
        float4 ea1 = ea4[1];

        uint4 v0 = yv[s];        // o = 2s    (lanes 0..7 -> line 0)
        uint4 v1 = yv[s + 8];    // o = 2s+1  (lanes 0..7 -> line 1)

        float m0, m1;
        {
            const __half2* h = (const __half2*)&v0;
            float2 f0 = __half22float2(h[0]);
            float2 f1 = __half22float2(h[1]);
            float2 f2 = __half22float2(h[2]);
            float2 f3 = __half22float2(h[3]);
            m0 = f0.x * ea0.x + f0.y * ea0.y + f1.x * ea0.z + f1.y * ea0.w
               + f2.x * ea1.x + f2.y * ea1.y + f3.x * ea1.z + f3.y * ea1.w;
        }
        {
            const __half2* h = (const __half2*)&v1;
            float2 f0 = __half22float2(h[0]);
            float2 f1 = __half22float2(h[1]);
            float2 f2 = __half22float2(h[2]);
            float2 f3 = __half22float2(h[3]);
            m1 = f0.x * ea0.x + f0.y * ea0.y + f1.x * ea0.z + f1.y * ea0.w
               + f2.x * ea1.x + f2.y * ea1.y + f3.x * ea1.z + f3.y * ea1.w;
        }

        int dst = ei[E + e];
        float* p = out + (long long)dst * 16 + 2 * s;
        asm volatile("red.global.add.v2.f32 [%0], {%1, %2};"
                     :: "l"(p), "f"(m0), "f"(m1) : "memory");
    }
}

// ---------------------------------------------------------------------------
// P3: out = relu(out)   (bias folded into the init)
// ---------------------------------------------------------------------------
__global__ void relu_kernel(float* __restrict__ out, int total4) {
    int i = blockIdx.x * blockDim.x + threadIdx.x;
    if (i >= total4) return;
    float4 v = ((float4*)out)[i];
    v.x = fmaxf(v.x, 0.f);
    v.y = fmaxf(v.y, 0.f);
    v.z = fmaxf(v.z, 0.f);
    v.w = fmaxf(v.w, 0.f);
    ((float4*)out)[i] = v;
}

// ---------------------------------------------------------------------------
// inputs (metadata order): x[N,16] f32, edge_index[2,E] i32, edge_attr[E,8]
//   f32, weight_matrix[8,16,16] f32, bias[16] f32, num_nodes
// output: [N,16] f32
//
// Launch order: 1 initA  2 precompute  3 initB  4 edge (ncu slot)  5 relu
// ---------------------------------------------------------------------------
extern "C" void kernel_launch(void* const* d_in, const int* in_sizes, int n_in,
                              void* d_out, int out_size) {
    const float* x = (const float*)d_in[0];
    const int* ei = (const int*)d_in[1];
    const float* eattr = (const float*)d_in[2];
    const float* W = (const float*)d_in[3];
    const float* bias = (const float*)d_in[4];

    int N = in_sizes[0] / 16;
    int E = in_sizes[2] / 8;
    float* out = (float*)d_out;

    int n4 = out_size / 4;
    int half4 = n4 / 2;

    // 1: init first half of out with bias
    init_out_kernel<<<(half4 + 255) / 256, 256>>>((float4*)out, bias, 0, half4);
    // 2: per-node precompute (4 nodes/thread, 128 nodes/warp, f32x2 FMA)
    {
        long long warps = ((long long)N + 127) / 128;
        long long threads = warps * 32;
        int blocks = (int)((threads + 127) / 128);
        precompute_y_kernel<<<blocks, 128>>>(x, W, N);
    }
    // 3: init second half of out with bias
    init_out_kernel<<<((n4 - half4) + 255) / 256, 256>>>((float4*)out, bias, half4, n4);
    // 4: edge gather/scatter  (profiled slot)
    {
        long long warps = ((long long)E + 7) / 8;
        long long threads = warps * 32;
        int blocks = (int)((threads + 255) / 256);
        edge_scatter_kernel<<<blocks, 256>>>(ei, eattr, out, E);
    }
    // 5: relu
    relu_kernel<<<(n4 + 255) / 256, 256>>>(out, n4);
}

// round 15
// speedup vs baseline: 1.2006x; 1.2006x over previous
#include <cuda_runtime.h>
#include <cuda_fp16.h>

// ---------------------------------------------------------------------------
// CustomGraphConv on GB300 — R15: R10 kernels + self-restoring accumulator
// (3 launches instead of 5).
//
//   msg[e,o]  = sum_{a,i} edge_attr[e,a] * W[a,o,i] * x[src_e, i]
//   aggr[n,o] = segment_sum over dst ; out = relu(aggr + bias)
//
// g_accum is zero at module load. Edge kernel red.adds into it; the final
// kernel emits relu(accum + bias) to d_out AND stores 0 back, restoring the
// zero invariant for the next call / graph replay. Same work every call.
//
// Precompute/edge are byte-level reverts to R10 (82.4us best): R11/R13/R14
// all showed R10's precompute is a local optimum; edge is ~4 wf/edge.
// ---------------------------------------------------------------------------

#define MAX_NODES 100000

// layout: [n][c=16][a=8] fp16, chunk c holds o = (c<8) ? 2c : 2(c-8)+1
__device__ __half g_yh[MAX_NODES * 128];      // 25.6 MB (L2-resident)
__device__ float  g_accum[MAX_NODES * 16];    // 6.4 MB, zero at load; each
                                              // call restores it to zero.

// ---------------------------------------------------------------------------
// P1: y[n][c(o)][a] = dot(W[a][o][:], x[n][:]). 4 nodes per thread
// (lane-strided) so warp-uniform W row loads (broadcast, L1-resident)
// amortize 4x. Exact R10 version.
// ---------------------------------------------------------------------------
__global__ void __launch_bounds__(128)
precompute_y_kernel(const float* __restrict__ x,
                    const float* __restrict__ W,
                    int N) {
    int lane = threadIdx.x & 31;
    int warp = (blockIdx.x * blockDim.x + threadIdx.x) >> 5;
    int n0 = warp * 128 + lane;

    float4 xv[4][4];
    int nidx[4];
#pragma unroll
    for (int nn = 0; nn < 4; ++nn) {
        int n = n0 + 32 * nn;
        if (n >= N) n = N - 1;       // duplicate writes of same data: benign
        nidx[nn] = n;
        const float4* xp = (const float4*)x + (long long)n * 4;
#pragma unroll
        for (int q = 0; q < 4; ++q) xv[nn][q] = xp[q];
    }

    const float4* W4 = (const float4*)W;   // row (a,o) at index (a*16+o)*4

#pragma unroll 2
    for (int o = 0; o < 16; ++o) {
        float acc[4][8];
#pragma unroll
        for (int a = 0; a < 8; ++a) {
            int row = a * 16 + o;
            float4 w0 = W4[row * 4 + 0];
            float4 w1 = W4[row * 4 + 1];
            float4 w2 = W4[row * 4 + 2];
            float4 w3 = W4[row * 4 + 3];
#pragma unroll
            for (int nn = 0; nn < 4; ++nn) {
                float v;
                v  = w0.x * xv[nn][0].x + w0.y * xv[nn][0].y
                   + w0.z * xv[nn][0].z + w0.w * xv[nn][0].w;
                v += w1.x * xv[nn][1].x + w1.y * xv[nn][1].y
                   + w1.z * xv[nn][1].z + w1.w * xv[nn][1].w;
                v += w2.x * xv[nn][2].x + w2.y * xv[nn][2].y
                   + w2.z * xv[nn][2].z + w2.w * xv[nn][2].w;
                v += w3.x * xv[nn][3].x + w3.y * xv[nn][3].y
                   + w3.z * xv[nn][3].z + w3.w * xv[nn][3].w;
                acc[nn][a] = v;
            }
        }
        // parity-permuted chunk: even o -> chunks 0..7, odd o -> chunks 8..15
        int c = (o & 1) * 8 + (o >> 1);
#pragma unroll
        for (int nn = 0; nn < 4; ++nn) {
            __half2 h0 = __floats2half2_rn(acc[nn][0], acc[nn][1]);
            __half2 h1 = __floats2half2_rn(acc[nn][2], acc[nn][3]);
            __half2 h2 = __floats2half2_rn(acc[nn][4], acc[nn][5]);
            __half2 h3 = __floats2half2_rn(acc[nn][6], acc[nn][7]);
            uint4 u;
            u.x = *(unsigned*)&h0;
            u.y = *(unsigned*)&h1;
            u.z = *(unsigned*)&h2;
            u.w = *(unsigned*)&h3;
            ((uint4*)g_yh)[(long long)nidx[nn] * 16 + c] = u;
        }
    }
}

// ---------------------------------------------------------------------------
// P2 (frozen from R10, target = g_accum): 8 lanes/edge, 8 edges/warp.
// Lane s loads chunks {s, s+8}: one 128B line each (2 wavefronts/edge).
// Chunk s = o=2s (all 8 a-values); chunk s+8 = o=2s+1. Register dot with
// ea[e][0..8]. ZERO shfl. ONE red.global.add.v2.f32 per lane at
// g_accum[dst][2s] (the 8 lanes' reds form one contiguous 64B burst).
// ---------------------------------------------------------------------------
__global__ void edge_scatter_kernel(const int* __restrict__ ei,
                                    const float* __restrict__ eattr,
                                    int E) {
    int lane = threadIdx.x & 31;
    int warp = (blockIdx.x * blockDim.x + threadIdx.x) >> 5;
    int g = lane >> 3;   // edge slot within warp (0..3)
    int s = lane & 7;    // sublane within edge

#pragma unroll
    for (int t = 0; t < 2; ++t) {
        int e = warp * 8 + t * 4 + g;
        if (e >= E) break;  // uniform across the 8-lane group

        int src = ei[e];
        const uint4* yv = (const uint4*)g_yh + (long long)src * 16;
        const float4* ea4 = (const float4*)(eattr + (long long)e * 8);
        float4 ea0 = ea4[0];
        float4 ea1 = ea4[1];

        uint4 v0 = yv[s];        // o = 2s    (lanes 0..7 -> line 0)
        uint4 v1 = yv[s + 8];    // o = 2s+1  (lanes 0..7 -> line 1)

        float m0, m1;
        {
            const __half2* h = (const __half2*)&v0;
            float2 f0 = __half22float2(h[0]);
            float2 f1 = __half22float2(h[1]);
            float2 f2 = __half22float2(h[2]);
            float2 f3 = __half22float2(h[3]);
            m0 = f0.x * ea0.x + f0.y * ea0.y + f1.x * ea0.z + f1.y * ea0.w
               + f2.x * ea1.x + f2.y * ea1.y + f3.x * ea1.z + f3.y * ea1.w;
        }
        {
            const __half2* h = (const __half2*)&v1;
            float2 f0 = __half22float2(h[0]);
            float2 f1 = __half22float2(h[1]);
            float2 f2 = __half22float2(h[2]);
            float2 f3 = __half22float2(h[3]);
            m1 = f0.x * ea0.x + f0.y * ea0.y + f1.x * ea0.z + f1.y * ea0.w
               + f2.x * ea1.x + f2.y * ea1.y + f3.x * ea1.z + f3.y * ea1.w;
        }

        int dst = ei[E + e];
        float* p = g_accum + (long long)dst * 16 + 2 * s;
        asm volatile("red.global.add.v2.f32 [%0], {%1, %2};"
                     :: "l"(p), "f"(m0), "f"(m1) : "memory");
    }
}

// ---------------------------------------------------------------------------
// P3: out = relu(accum + bias); accum = 0 (restores the zero invariant for
// the next call / graph replay).
// ---------------------------------------------------------------------------
__global__ void finalize_kernel(float4* __restrict__ out,
                                const float* __restrict__ bias,
                                int total4) {
    int i = blockIdx.x * blockDim.x + threadIdx.x;
    if (i >= total4) return;
    float4 v = ((float4*)g_accum)[i];
    float4 b = ((const float4*)bias)[i & 3];
    v.x = fmaxf(v.x + b.x, 0.f);
    v.y = fmaxf(v.y + b.y, 0.f);
    v.z = fmaxf(v.z + b.z, 0.f);
    v.w = fmaxf(v.w + b.w, 0.f);
    out[i] = v;
    ((float4*)g_accum)[i] = make_float4(0.f, 0.f, 0.f, 0.f);
}

// ---------------------------------------------------------------------------
// inputs (metadata order): x[N,16] f32, edge_index[2,E] i32, edge_attr[E,8]
//   f32, weight_matrix[8,16,16] f32, bias[16] f32, num_nodes
// output: [N,16] f32
//
// Launch order: 1 precompute  2 edge  3 finalize
// ---------------------------------------------------------------------------
extern "C" void kernel_launch(void* const* d_in, const int* in_sizes, int n_in,
                              void* d_out, int out_size) {
    const float* x = (const float*)d_in[0];
    const int* ei = (const int*)d_in[1];
    const float* eattr = (const float*)d_in[2];
    const float* W = (const float*)d_in[3];
    const float* bias = (const float*)d_in[4];

    int N = in_sizes[0] / 16;
    int E = in_sizes[2] / 8;
    float* out = (float*)d_out;

    // 1: per-node precompute (4 nodes/thread, 128 nodes/warp)
    {
        long long warps = ((long long)N + 127) / 128;
        long long threads = warps * 32;
        int blocks = (int)((threads + 127) / 128);
        precompute_y_kernel<<<blocks, 128>>>(x, W, N);
    }
    // 2: edge gather/scatter into g_accum
    {
        long long warps = ((long long)E + 7) / 8;
        long long threads = warps * 32;
        int blocks = (int)((threads + 255) / 256);
        edge_scatter_kernel<<<blocks, 256>>>(ei, eattr, E);
    }
    // 3: finalize: out = relu(accum + bias), accum -> 0
    {
        int total4 = out_size / 4;
        finalize_kernel<<<(total4 + 255) / 256, 256>>>((float4*)out, bias, total4);
    }
}